// round 1
// baseline (speedup 1.0000x reference)
#include <cuda_runtime.h>

#define BB 2
#define LL 1024
#define HH 768
#define DI 1536
#define NSTATE 16
#define KCONV 4
#define RR 48
#define MM (BB*LL)          // 2048
#define D1 (2*DI*4)         // 12288
#define D2 (2*DI)           // 3072
#define D3 (4*DI)           // 6144

// ---------------- scratch (device globals: no allocation allowed) ----------------
__device__ float g_T1[(size_t)MM*D1];     // silu(x @ in_up_w^T)            [2048,12288]
__device__ float g_P [(size_t)MM*D2];     // in_down proj (hs | gate)       [2048,3072]
__device__ float g_HS[(size_t)MM*DI];     // silu(conv(hs))                 [2048,1536]
__device__ float g_XPW[128*DI];           // x_proj_w padded to 128 rows
__device__ float g_SSMP[(size_t)MM*128];  // [dt48 | B16 | C16 | pad]       [2048,128]
__device__ float g_DT[(size_t)MM*DI];     // softplus(dt proj)              [2048,1536]
__device__ float g_YS[(size_t)MM*DI];     // scan output                    [2048,1536]
__device__ float g_Y [(size_t)MM*DI];     // combined (pre out_up)          [2048,1536]
__device__ float g_T4[(size_t)MM*D3];     // silu(y @ out_up_w^T)           [2048,6144]

__device__ __forceinline__ float siluf(float x) {
    return x / (1.f + __expf(-x));
}
__device__ __forceinline__ float softplusf(float x) {
    return (x > 20.f) ? x : log1pf(__expf(x));
}

// ---------------- generic sgemm: C[m,n] = epi(sum_k A[m,k]*W[n,k] (+bias[n])) ----
// BM=BN=128, BK=8, 256 threads, 8x8 register tile per thread.
// All M,N multiples of 128 and all K multiples of 8 by construction -> no guards.
template<int EPI>
__global__ void __launch_bounds__(256) sgemm_kernel(
    const float* __restrict__ A, const float* __restrict__ W,
    const float* __restrict__ bias, float* __restrict__ C,
    int K, int lda, int ldw, int ldc)
{
    __shared__ __align__(16) float As[8][128];
    __shared__ __align__(16) float Bs[8][128];

    const int tid = threadIdx.x;
    const long bm = (long)blockIdx.y * 128;
    const long bn = (long)blockIdx.x * 128;
    const int tx = tid & 15;      // 16 thread cols
    const int ty = tid >> 4;      // 16 thread rows
    const int lr = tid >> 1;      // load row 0..127
    const int lc = (tid & 1) * 4; // load col 0 or 4

    const float* Ap = A + (bm + lr) * (long)lda + lc;
    const float* Wp = W + (bn + lr) * (long)ldw + lc;

    float acc[8][8];
#pragma unroll
    for (int i = 0; i < 8; i++)
#pragma unroll
        for (int j = 0; j < 8; j++) acc[i][j] = 0.f;

    for (int k0 = 0; k0 < K; k0 += 8) {
        float4 av = *(const float4*)(Ap + k0);
        float4 wv = *(const float4*)(Wp + k0);
        __syncthreads();
        As[lc + 0][lr] = av.x; As[lc + 1][lr] = av.y;
        As[lc + 2][lr] = av.z; As[lc + 3][lr] = av.w;
        Bs[lc + 0][lr] = wv.x; Bs[lc + 1][lr] = wv.y;
        Bs[lc + 2][lr] = wv.z; Bs[lc + 3][lr] = wv.w;
        __syncthreads();
#pragma unroll
        for (int k = 0; k < 8; k++) {
            float4 a0 = *(const float4*)&As[k][ty * 8];
            float4 a1 = *(const float4*)&As[k][ty * 8 + 4];
            float4 b0 = *(const float4*)&Bs[k][tx * 8];
            float4 b1 = *(const float4*)&Bs[k][tx * 8 + 4];
            float ar[8] = {a0.x, a0.y, a0.z, a0.w, a1.x, a1.y, a1.z, a1.w};
            float br[8] = {b0.x, b0.y, b0.z, b0.w, b1.x, b1.y, b1.z, b1.w};
#pragma unroll
            for (int i = 0; i < 8; i++)
#pragma unroll
                for (int j = 0; j < 8; j++)
                    acc[i][j] = fmaf(ar[i], br[j], acc[i][j]);
        }
    }

#pragma unroll
    for (int i = 0; i < 8; i++) {
        long m = bm + ty * 8 + i;
#pragma unroll
        for (int j = 0; j < 8; j++) {
            long n = bn + tx * 8 + j;
            float v = acc[i][j];
            if (EPI == 1) v = siluf(v);
            else if (EPI == 2) v = softplusf(v + bias[n]);
            C[m * (long)ldc + n] = v;
        }
    }
}

// ---------------- depthwise causal conv (K=4) + SiLU --------------------------
__global__ void conv_kernel(const float* __restrict__ cw, const float* __restrict__ cb)
{
    int idx = blockIdx.x * blockDim.x + threadIdx.x;
    if (idx >= MM * DI) return;
    int d = idx % DI;
    int m = idx / DI;
    int l = m & (LL - 1);
    float acc = cb[d];
#pragma unroll
    for (int k = 0; k < KCONV; k++) {
        int ls = l - (KCONV - 1) + k;
        if (ls >= 0)
            acc = fmaf(g_P[(long)(m - (KCONV - 1) + k) * D2 + d], cw[d * KCONV + k], acc);
    }
    g_HS[idx] = siluf(acc);
}

// ---------------- pad x_proj_w [80,1536] -> [128,1536] zero-filled -------------
__global__ void pad_xpw_kernel(const float* __restrict__ xw)
{
    int idx = blockIdx.x * blockDim.x + threadIdx.x;
    if (idx >= 128 * DI) return;
    int n = idx / DI;
    int d = idx % DI;
    g_XPW[idx] = (n < RR + 2 * NSTATE) ? xw[n * DI + d] : 0.f;
}

// ---------------- selective scan: 16 lanes (one per state n) per (b,d) --------
__global__ void scan_kernel(const float* __restrict__ A_log)
{
    int t = blockIdx.x * blockDim.x + threadIdx.x;
    int gid = t >> 4;           // (b,d) group
    int n = t & 15;             // state index
    if (gid >= BB * DI) return;
    int b = gid / DI;
    int d = gid - b * DI;

    float An = -__expf(A_log[d * NSTATE + n]);
    float s = 0.f;
    const float* dtp = g_DT + (long)b * LL * DI + d;
    const float* hsp = g_HS + (long)b * LL * DI + d;
    const float* sp  = g_SSMP + (long)b * LL * 128;
    float* yp = g_YS + (long)b * LL * DI + d;

    for (int l = 0; l < LL; l++) {
        float dtv = dtp[(long)l * DI];
        float hv  = hsp[(long)l * DI];
        float bv  = sp[l * 128 + RR + n];
        float cv  = sp[l * 128 + RR + NSTATE + n];
        s = fmaf(__expf(dtv * An), s, dtv * bv * hv);
        float p = s * cv;
        p += __shfl_xor_sync(0xffffffffu, p, 8);
        p += __shfl_xor_sync(0xffffffffu, p, 4);
        p += __shfl_xor_sync(0xffffffffu, p, 2);
        p += __shfl_xor_sync(0xffffffffu, p, 1);
        if (n == 0) yp[(long)l * DI] = p;
    }
}

// ---------------- combine: y = (ys + hs*D) * silu(gate) -----------------------
__global__ void combine_kernel(const float* __restrict__ Dv)
{
    int idx = blockIdx.x * blockDim.x + threadIdx.x;
    if (idx >= MM * DI) return;
    int d = idx % DI;
    int m = idx / DI;
    float g = g_P[(long)m * D2 + DI + d];
    g_Y[idx] = (g_YS[idx] + g_HS[idx] * Dv[d]) * siluf(g);
}

// ---------------- launch ------------------------------------------------------
extern "C" void kernel_launch(void* const* d_in, const int* in_sizes, int n_in,
                              void* d_out, int out_size)
{
    const float* x    = (const float*)d_in[0];
    const float* iuw  = (const float*)d_in[1];   // [12288, 768]
    const float* idw  = (const float*)d_in[2];   // [3072, 12288]
    const float* cw   = (const float*)d_in[3];   // [1536, 1, 4]
    const float* cb   = (const float*)d_in[4];   // [1536]
    const float* xpw  = (const float*)d_in[5];   // [80, 1536]
    const float* dtw  = (const float*)d_in[6];   // [1536, 48]
    const float* dtb  = (const float*)d_in[7];   // [1536]
    const float* alog = (const float*)d_in[8];   // [1536, 16]
    const float* Dv   = (const float*)d_in[9];   // [1536]
    const float* ouw  = (const float*)d_in[10];  // [6144, 1536]
    const float* odw  = (const float*)d_in[11];  // [768, 6144]
    float* out = (float*)d_out;

    float *T1, *P, *HS, *XPW, *SSMP, *DT, *YS, *Y, *T4;
    cudaGetSymbolAddress((void**)&T1,   g_T1);
    cudaGetSymbolAddress((void**)&P,    g_P);
    cudaGetSymbolAddress((void**)&HS,   g_HS);
    cudaGetSymbolAddress((void**)&XPW,  g_XPW);
    cudaGetSymbolAddress((void**)&SSMP, g_SSMP);
    cudaGetSymbolAddress((void**)&DT,   g_DT);
    cudaGetSymbolAddress((void**)&YS,   g_YS);
    cudaGetSymbolAddress((void**)&Y,    g_Y);
    cudaGetSymbolAddress((void**)&T4,   g_T4);

    // 1) T1 = silu(x @ in_up_w^T)              [2048, 12288]
    sgemm_kernel<1><<<dim3(D1 / 128, MM / 128), 256>>>(x, iuw, nullptr, T1, HH, HH, HH, D1);
    // 2) P = T1 @ in_down_w^T                  [2048, 3072]
    sgemm_kernel<0><<<dim3(D2 / 128, MM / 128), 256>>>(T1, idw, nullptr, P, D1, D1, D1, D2);
    // 3) HS = silu(causal depthwise conv(hs) + b)
    conv_kernel<<<(MM * DI + 255) / 256, 256>>>(cw, cb);
    // 4) pad x_proj_w to 128 rows
    pad_xpw_kernel<<<(128 * DI + 255) / 256, 256>>>(xpw);
    // 5) SSMP = HS @ XPW^T                     [2048, 128] (80 valid)
    sgemm_kernel<0><<<dim3(1, MM / 128), 256>>>(HS, XPW, nullptr, SSMP, DI, DI, DI, 128);
    // 6) DT = softplus(SSMP[:, :48] @ dt_w^T + dt_b)   [2048, 1536]
    sgemm_kernel<2><<<dim3(DI / 128, MM / 128), 256>>>(SSMP, dtw, dtb, DT, RR, 128, RR, DI);
    // 7) selective scan -> YS
    scan_kernel<<<(BB * DI * 16 + 255) / 256, 256>>>(alog);
    // 8) Y = (YS + HS*D) * silu(gate)
    combine_kernel<<<(MM * DI + 255) / 256, 256>>>(Dv);
    // 9) T4 = silu(Y @ out_up_w^T)             [2048, 6144]
    sgemm_kernel<1><<<dim3(D3 / 128, MM / 128), 256>>>(Y, ouw, nullptr, T4, DI, DI, DI, D3);
    // 10) out = T4 @ out_down_w^T              [2048, 768]
    sgemm_kernel<0><<<dim3(HH / 128, MM / 128), 256>>>(T4, odw, nullptr, out, D3, D3, D3, HH);
}

// round 4
// speedup vs baseline: 1.0884x; 1.0884x over previous
#include <cuda_runtime.h>

#define BB 2
#define LL 1024
#define HH 768
#define DI 1536
#define NSTATE 16
#define KCONV 4
#define RR 48
#define MM (BB*LL)          // 2048
#define D1 (2*DI*4)         // 12288
#define D2 (2*DI)           // 3072
#define D3 (4*DI)           // 6144

// ---------------- scratch (device globals: no allocation allowed) ----------------
__device__ float g_T1[(size_t)MM*D1];     // silu(x @ in_up_w^T)            [2048,12288]
__device__ float g_P [(size_t)MM*D2];     // in_down proj (hs | gate)       [2048,3072]
__device__ float g_HS[(size_t)MM*DI];     // silu(conv(hs))                 [2048,1536]
__device__ float g_XPW[128*DI];           // x_proj_w padded to 128 rows
__device__ float g_SSMP[(size_t)MM*128];  // [dt48 | B16 | C16 | pad]       [2048,128]
__device__ float g_DT[(size_t)MM*DI];     // softplus(dt proj)              [2048,1536]
__device__ float g_YS[(size_t)MM*DI];     // scan output                    [2048,1536]
__device__ float g_Y [(size_t)MM*DI];     // combined (pre out_up)          [2048,1536]
__device__ float g_T4[(size_t)MM*D3];     // silu(y @ out_up_w^T)           [2048,6144]

__device__ __forceinline__ float siluf(float x) {
    return x / (1.f + __expf(-x));
}
__device__ __forceinline__ float softplusf(float x) {
    return (x > 20.f) ? x : log1pf(__expf(x));
}

// ---------------- sgemm with packed fp32x2 FMA --------------------------------
// C[m,n] = epi(sum_k A[m,k]*W[n,k] (+bias[n]))
// BM=BN=128, BK=8, 256 threads, 8x8 register tile per thread, acc as 8x4 f32x2.
// Double-buffered shared memory: one __syncthreads per k-tile.
// All M,N multiples of 128 and all K multiples of 8 by construction.
template<int EPI>
__global__ void __launch_bounds__(256) sgemm_kernel(
    const float* __restrict__ A, const float* __restrict__ W,
    const float* __restrict__ bias, float* __restrict__ C,
    int K, int lda, int ldw, int ldc)
{
    __shared__ __align__(16) float As[2][8][128];
    __shared__ __align__(16) float Bs[2][8][128];

    const int tid = threadIdx.x;
    const long bm = (long)blockIdx.y * 128;
    const long bn = (long)blockIdx.x * 128;
    const int tx = tid & 15;      // 16 thread cols
    const int ty = tid >> 4;      // 16 thread rows
    const int lr = tid >> 1;      // load row 0..127
    const int lc = (tid & 1) * 4; // load col 0 or 4

    const float* Ap = A + (bm + lr) * (long)lda + lc;
    const float* Wp = W + (bn + lr) * (long)ldw + lc;

    unsigned long long acc[8][4];
#pragma unroll
    for (int i = 0; i < 8; i++)
#pragma unroll
        for (int j = 0; j < 4; j++) acc[i][j] = 0ULL;

    const int T = K >> 3;

    // prologue: tile0 -> buf0, prefetch tile1 into regs
    float4 av = *(const float4*)(Ap);
    float4 wv = *(const float4*)(Wp);
    As[0][lc + 0][lr] = av.x; As[0][lc + 1][lr] = av.y;
    As[0][lc + 2][lr] = av.z; As[0][lc + 3][lr] = av.w;
    Bs[0][lc + 0][lr] = wv.x; Bs[0][lc + 1][lr] = wv.y;
    Bs[0][lc + 2][lr] = wv.z; Bs[0][lc + 3][lr] = wv.w;
    if (T > 1) {
        av = *(const float4*)(Ap + 8);
        wv = *(const float4*)(Wp + 8);
    }
    __syncthreads();

    int p = 0;
    for (int t = 0; t < T; t++) {
        // store tile t+1 into the other buffer (its last readers synced at end
        // of iteration t-1, so no hazard), then prefetch tile t+2.
        if (t + 1 < T) {
            int q = p ^ 1;
            As[q][lc + 0][lr] = av.x; As[q][lc + 1][lr] = av.y;
            As[q][lc + 2][lr] = av.z; As[q][lc + 3][lr] = av.w;
            Bs[q][lc + 0][lr] = wv.x; Bs[q][lc + 1][lr] = wv.y;
            Bs[q][lc + 2][lr] = wv.z; Bs[q][lc + 3][lr] = wv.w;
        }
        if (t + 2 < T) {
            av = *(const float4*)(Ap + (long)(t + 2) * 8);
            wv = *(const float4*)(Wp + (long)(t + 2) * 8);
        }
#pragma unroll
        for (int k = 0; k < 8; k++) {
            float4 a0 = *(const float4*)&As[p][k][ty * 8];
            float4 a1 = *(const float4*)&As[p][k][ty * 8 + 4];
            ulonglong2 b0 = *(const ulonglong2*)&Bs[p][k][tx * 8];
            ulonglong2 b1 = *(const ulonglong2*)&Bs[p][k][tx * 8 + 4];
            unsigned long long bq[4] = {b0.x, b0.y, b1.x, b1.y};
            float ar[8] = {a0.x, a0.y, a0.z, a0.w, a1.x, a1.y, a1.z, a1.w};
            unsigned long long pa[8];
#pragma unroll
            for (int i = 0; i < 8; i++)
                asm("mov.b64 %0, {%1, %1};" : "=l"(pa[i]) : "f"(ar[i]));
#pragma unroll
            for (int i = 0; i < 8; i++)
#pragma unroll
                for (int j = 0; j < 4; j++)
                    asm("fma.rn.f32x2 %0, %1, %2, %0;"
                        : "+l"(acc[i][j]) : "l"(pa[i]), "l"(bq[j]));
        }
        __syncthreads();
        p ^= 1;
    }

#pragma unroll
    for (int i = 0; i < 8; i++) {
        long m = bm + ty * 8 + i;
#pragma unroll
        for (int j = 0; j < 4; j++) {
            long n = bn + tx * 8 + 2 * j;
            float2 v;
            asm("mov.b64 {%0, %1}, %2;" : "=f"(v.x), "=f"(v.y) : "l"(acc[i][j]));
            if (EPI == 1) { v.x = siluf(v.x); v.y = siluf(v.y); }
            else if (EPI == 2) {
                v.x = softplusf(v.x + bias[n]);
                v.y = softplusf(v.y + bias[n + 1]);
            }
            *(float2*)&C[m * (long)ldc + n] = v;
        }
    }
}

// ---------------- depthwise causal conv (K=4) + SiLU --------------------------
__global__ void conv_kernel(const float* __restrict__ cw, const float* __restrict__ cb)
{
    int idx = blockIdx.x * blockDim.x + threadIdx.x;
    if (idx >= MM * DI) return;
    int d = idx % DI;
    int m = idx / DI;
    int l = m & (LL - 1);
    float acc = cb[d];
#pragma unroll
    for (int k = 0; k < KCONV; k++) {
        int ls = l - (KCONV - 1) + k;
        if (ls >= 0)
            acc = fmaf(g_P[(long)(m - (KCONV - 1) + k) * D2 + d], cw[d * KCONV + k], acc);
    }
    g_HS[idx] = siluf(acc);
}

// ---------------- pad x_proj_w [80,1536] -> [128,1536] zero-filled -------------
__global__ void pad_xpw_kernel(const float* __restrict__ xw)
{
    int idx = blockIdx.x * blockDim.x + threadIdx.x;
    if (idx >= 128 * DI) return;
    int n = idx / DI;
    int d = idx % DI;
    g_XPW[idx] = (n < RR + 2 * NSTATE) ? xw[n * DI + d] : 0.f;
}

// ---------------- selective scan: 16 lanes (one per state n) per (b,d) --------
__global__ void scan_kernel(const float* __restrict__ A_log)
{
    int t = blockIdx.x * blockDim.x + threadIdx.x;
    int gid = t >> 4;           // (b,d) group
    int n = t & 15;             // state index
    if (gid >= BB * DI) return;
    int b = gid / DI;
    int d = gid - b * DI;

    float An = -__expf(A_log[d * NSTATE + n]);
    float s = 0.f;
    const float* dtp = g_DT + (long)b * LL * DI + d;
    const float* hsp = g_HS + (long)b * LL * DI + d;
    const float* sp  = g_SSMP + (long)b * LL * 128;
    float* yp = g_YS + (long)b * LL * DI + d;

    for (int l = 0; l < LL; l++) {
        float dtv = dtp[(long)l * DI];
        float hv  = hsp[(long)l * DI];
        float bv  = sp[l * 128 + RR + n];
        float cv  = sp[l * 128 + RR + NSTATE + n];
        s = fmaf(__expf(dtv * An), s, dtv * bv * hv);
        float p = s * cv;
        p += __shfl_xor_sync(0xffffffffu, p, 8);
        p += __shfl_xor_sync(0xffffffffu, p, 4);
        p += __shfl_xor_sync(0xffffffffu, p, 2);
        p += __shfl_xor_sync(0xffffffffu, p, 1);
        if (n == 0) yp[(long)l * DI] = p;
    }
}

// ---------------- combine: y = (ys + hs*D) * silu(gate) -----------------------
__global__ void combine_kernel(const float* __restrict__ Dv)
{
    int idx = blockIdx.x * blockDim.x + threadIdx.x;
    if (idx >= MM * DI) return;
    int d = idx % DI;
    int m = idx / DI;
    float g = g_P[(long)m * D2 + DI + d];
    g_Y[idx] = (g_YS[idx] + g_HS[idx] * Dv[d]) * siluf(g);
}

// ---------------- launch ------------------------------------------------------
extern "C" void kernel_launch(void* const* d_in, const int* in_sizes, int n_in,
                              void* d_out, int out_size)
{
    const float* x    = (const float*)d_in[0];
    const float* iuw  = (const float*)d_in[1];   // [12288, 768]
    const float* idw  = (const float*)d_in[2];   // [3072, 12288]
    const float* cw   = (const float*)d_in[3];   // [1536, 1, 4]
    const float* cb   = (const float*)d_in[4];   // [1536]
    const float* xpw  = (const float*)d_in[5];   // [80, 1536]
    const float* dtw  = (const float*)d_in[6];   // [1536, 48]
    const float* dtb  = (const float*)d_in[7];   // [1536]
    const float* alog = (const float*)d_in[8];   // [1536, 16]
    const float* Dv   = (const float*)d_in[9];   // [1536]
    const float* ouw  = (const float*)d_in[10];  // [6144, 1536]
    const float* odw  = (const float*)d_in[11];  // [768, 6144]
    float* out = (float*)d_out;

    float *T1, *P, *HS, *XPW, *SSMP, *DT, *YS, *Y, *T4;
    cudaGetSymbolAddress((void**)&T1,   g_T1);
    cudaGetSymbolAddress((void**)&P,    g_P);
    cudaGetSymbolAddress((void**)&HS,   g_HS);
    cudaGetSymbolAddress((void**)&XPW,  g_XPW);
    cudaGetSymbolAddress((void**)&SSMP, g_SSMP);
    cudaGetSymbolAddress((void**)&DT,   g_DT);
    cudaGetSymbolAddress((void**)&YS,   g_YS);
    cudaGetSymbolAddress((void**)&Y,    g_Y);
    cudaGetSymbolAddress((void**)&T4,   g_T4);

    // 1) T1 = silu(x @ in_up_w^T)              [2048, 12288]
    sgemm_kernel<1><<<dim3(D1 / 128, MM / 128), 256>>>(x, iuw, nullptr, T1, HH, HH, HH, D1);
    // 2) P = T1 @ in_down_w^T                  [2048, 3072]
    sgemm_kernel<0><<<dim3(D2 / 128, MM / 128), 256>>>(T1, idw, nullptr, P, D1, D1, D1, D2);
    // 3) HS = silu(causal depthwise conv(hs) + b)
    conv_kernel<<<(MM * DI + 255) / 256, 256>>>(cw, cb);
    // 4) pad x_proj_w to 128 rows
    pad_xpw_kernel<<<(128 * DI + 255) / 256, 256>>>(xpw);
    // 5) SSMP = HS @ XPW^T                     [2048, 128] (80 valid)
    sgemm_kernel<0><<<dim3(1, MM / 128), 256>>>(HS, XPW, nullptr, SSMP, DI, DI, DI, 128);
    // 6) DT = softplus(SSMP[:, :48] @ dt_w^T + dt_b)   [2048, 1536]
    sgemm_kernel<2><<<dim3(DI / 128, MM / 128), 256>>>(SSMP, dtw, dtb, DT, RR, 128, RR, DI);
    // 7) selective scan -> YS
    scan_kernel<<<(BB * DI * 16 + 255) / 256, 256>>>(alog);
    // 8) Y = (YS + HS*D) * silu(gate)
    combine_kernel<<<(MM * DI + 255) / 256, 256>>>(Dv);
    // 9) T4 = silu(Y @ out_up_w^T)             [2048, 6144]
    sgemm_kernel<1><<<dim3(D3 / 128, MM / 128), 256>>>(Y, ouw, nullptr, T4, DI, DI, DI, D3);
    // 10) out = T4 @ out_down_w^T              [2048, 768]
    sgemm_kernel<0><<<dim3(HH / 128, MM / 128), 256>>>(T4, odw, nullptr, out, D3, D3, D3, HH);
}

// round 6
// speedup vs baseline: 2.7051x; 2.4854x over previous
#include <cuda_runtime.h>
#include <cstdint>

#define BB 2
#define LL 1024
#define HH 768
#define DI 1536
#define NSTATE 16
#define KCONV 4
#define RR 48
#define MM (BB*LL)          // 2048
#define D1 (2*DI*4)         // 12288
#define D2 (2*DI)           // 3072
#define D3 (4*DI)           // 6144
#define NSPLIT 8

// ---------------- scratch (device globals: no allocation allowed) --------------
__device__ float g_T1[(size_t)MM*D1];
__device__ float g_P [(size_t)MM*D2];
__device__ float g_HS[(size_t)MM*DI];
__device__ float g_XPW[128*DI];
__device__ float g_SPX[(size_t)NSPLIT*MM*128];  // split-K partials for x_proj
__device__ float g_SSMP[(size_t)MM*128];
__device__ float g_DT[(size_t)MM*DI];
__device__ float g_YS[(size_t)MM*DI];
__device__ float g_Y [(size_t)MM*DI];
__device__ float g_T4[(size_t)MM*D3];

__device__ __forceinline__ float siluf(float x) { return x / (1.f + __expf(-x)); }
__device__ __forceinline__ float softplusf(float x) { return (x > 20.f) ? x : log1pf(__expf(x)); }

__device__ __forceinline__ uint32_t smem_u32(const void* p) {
    uint32_t a;
    asm("{ .reg .u64 t; cvta.to.shared.u64 t, %1; cvt.u32.u64 %0, t; }" : "=r"(a) : "l"(p));
    return a;
}
__device__ __forceinline__ void ldsm4(uint32_t* r, uint32_t addr) {
    asm volatile("ldmatrix.sync.aligned.m8n8.x4.shared.b16 {%0,%1,%2,%3}, [%4];"
        : "=r"(r[0]), "=r"(r[1]), "=r"(r[2]), "=r"(r[3]) : "r"(addr));
}
__device__ __forceinline__ void mma_bf16(float* d, const uint32_t* a, const uint32_t* b) {
    asm volatile("mma.sync.aligned.m16n8k16.row.col.f32.bf16.bf16.f32 "
        "{%0,%1,%2,%3}, {%4,%5,%6,%7}, {%8,%9}, {%0,%1,%2,%3};"
        : "+f"(d[0]), "+f"(d[1]), "+f"(d[2]), "+f"(d[3])
        : "r"(a[0]), "r"(a[1]), "r"(a[2]), "r"(a[3]), "r"(b[0]), "r"(b[1]));
}
__device__ __forceinline__ void st16(uint32_t a, const uint32_t* r) {
    asm volatile("st.shared.v4.b32 [%0], {%1,%2,%3,%4};"
        :: "r"(a), "r"(r[0]), "r"(r[1]), "r"(r[2]), "r"(r[3]) : "memory");
}
// 8 fp32 -> 4 u32 of bf16-hi (exact truncation) + 4 u32 of bf16-lo (residual)
__device__ __forceinline__ void cvt8(const float4& v0, const float4& v1,
                                     uint32_t* hi, uint32_t* lo)
{
    const float f[8] = {v0.x, v0.y, v0.z, v0.w, v1.x, v1.y, v1.z, v1.w};
#pragma unroll
    for (int j = 0; j < 4; j++) {
        uint32_t x = __float_as_uint(f[2 * j]);
        uint32_t y = __float_as_uint(f[2 * j + 1]);
        asm("prmt.b32 %0, %1, %2, 0x7632;" : "=r"(hi[j]) : "r"(x), "r"(y));
        float lx = f[2 * j]     - __uint_as_float(x & 0xFFFF0000u);
        float ly = f[2 * j + 1] - __uint_as_float(y & 0xFFFF0000u);
        asm("cvt.rn.satfinite.bf16x2.f32 %0, %1, %2;" : "=r"(lo[j]) : "f"(ly), "f"(lx));
    }
}

// ================= HMMA bf16 split GEMM: C = epi(A @ W^T) ======================
// CTA 128x128, 256 threads (8 warps 4x2, warp tile 32x64), K-chunk = 32 fp32.
// smem row = 32 bf16 padded to 80 B (conflict-free ldmatrix). Tiles per buffer:
// Ah, Al, Bh, Bl. Double buffered.
#define ROWB 80u
#define TILEB (128u * ROWB)          // 10240 B
#define BUFB  (4u * TILEB)           // 40960 B
#define HSMEM (2 * 40960)

template<int EPI>
__global__ void __launch_bounds__(256, 1) hgemm_kernel(
    const float* __restrict__ A, const float* __restrict__ W,
    float* __restrict__ C, int lda, int ldw, int ldc,
    int kPerSplit, long csplit)
{
    extern __shared__ char smem[];
    const uint32_t sb = smem_u32(smem);
    const int tid = threadIdx.x;
    const long bm = (long)blockIdx.y * 128;
    const long bn = (long)blockIdx.x * 128;
    const int koff = blockIdx.z * kPerSplit;
    float* Cout = C + (long)blockIdx.z * csplit;

    // --- producer indexing: 2 threads per row, 16 fp32 each -------------------
    const int r = tid >> 1, half = tid & 1;
    const float4* Ap = (const float4*)(A + (bm + r) * (long)lda + koff) + half * 4;
    const float4* Wp = (const float4*)(W + (bn + r) * (long)ldw + koff) + half * 4;
    const uint32_t soff = (uint32_t)r * ROWB + (uint32_t)half * 32u;

    // --- consumer indexing -----------------------------------------------------
    const int wid = tid >> 5, lane = tid & 31;
    const int wm = wid >> 1, wn = wid & 1;
    const uint32_t a_addr = (uint32_t)((wm * 32 + (lane & 15)) * ROWB + ((lane >> 4) << 3) * 2);
    const uint32_t b_row  = (uint32_t)(wn * 64 + (lane & 7) + ((lane >> 4) & 1) * 8);
    const uint32_t b_addr = b_row * ROWB + (uint32_t)(((lane >> 3) & 1) * 16);

    float acc[2][8][4];
#pragma unroll
    for (int f = 0; f < 2; f++)
#pragma unroll
        for (int g = 0; g < 8; g++)
#pragma unroll
            for (int e = 0; e < 4; e++) acc[f][g][e] = 0.f;

    const int Tc = kPerSplit >> 5;
    float4 av[4], wv[4];

#define LOADCH(t) { const float4* ap_ = Ap + (long)(t) * 8; const float4* wp_ = Wp + (long)(t) * 8; \
    av[0] = ap_[0]; av[1] = ap_[1]; av[2] = ap_[2]; av[3] = ap_[3]; \
    wv[0] = wp_[0]; wv[1] = wp_[1]; wv[2] = wp_[2]; wv[3] = wp_[3]; }

#define STORECH(bb) { uint32_t h_[4], l_[4]; \
    cvt8(av[0], av[1], h_, l_); st16((bb) + soff,      h_); st16((bb) + TILEB + soff,      l_); \
    cvt8(av[2], av[3], h_, l_); st16((bb) + soff + 16, h_); st16((bb) + TILEB + soff + 16, l_); \
    cvt8(wv[0], wv[1], h_, l_); st16((bb) + 2*TILEB + soff,      h_); st16((bb) + 3*TILEB + soff,      l_); \
    cvt8(wv[2], wv[3], h_, l_); st16((bb) + 2*TILEB + soff + 16, h_); st16((bb) + 3*TILEB + soff + 16, l_); }

    LOADCH(0);
    STORECH(sb);
    if (Tc > 1) LOADCH(1);
    __syncthreads();

    for (int t = 0; t < Tc; t++) {
        const uint32_t base = sb + (uint32_t)(t & 1) * BUFB;
        if (t + 1 < Tc) {
            const uint32_t nb = sb + (uint32_t)((t + 1) & 1) * BUFB;
            STORECH(nb);
        }
        if (t + 2 < Tc) LOADCH(t + 2);

#pragma unroll
        for (int s = 0; s < 2; s++) {
            uint32_t ah[2][4], al[2][4];
#pragma unroll
            for (int f = 0; f < 2; f++) {
                uint32_t ad = base + a_addr + (uint32_t)(f * 16) * ROWB + (uint32_t)(s * 32);
                ldsm4(ah[f], ad);
                ldsm4(al[f], ad + TILEB);
            }
            uint32_t bh[8][2], bl[8][2];
#pragma unroll
            for (int g2 = 0; g2 < 4; g2++) {
                uint32_t bd = base + 2 * TILEB + b_addr + (uint32_t)(g2 * 16) * ROWB + (uint32_t)(s * 32);
                uint32_t q[4];
                ldsm4(q, bd);
                bh[2*g2][0] = q[0]; bh[2*g2][1] = q[1];
                bh[2*g2+1][0] = q[2]; bh[2*g2+1][1] = q[3];
                ldsm4(q, bd + TILEB);
                bl[2*g2][0] = q[0]; bl[2*g2][1] = q[1];
                bl[2*g2+1][0] = q[2]; bl[2*g2+1][1] = q[3];
            }
#pragma unroll
            for (int f = 0; f < 2; f++)
#pragma unroll
                for (int g = 0; g < 8; g++) {
                    mma_bf16(acc[f][g], ah[f], bh[g]);
                    mma_bf16(acc[f][g], ah[f], bl[g]);
                    mma_bf16(acc[f][g], al[f], bh[g]);
                }
        }
        __syncthreads();
    }

    // --- epilogue ---------------------------------------------------------------
#pragma unroll
    for (int f = 0; f < 2; f++) {
        const long row = bm + wm * 32 + f * 16 + (lane >> 2);
#pragma unroll
        for (int g = 0; g < 8; g++) {
            const long col = bn + wn * 64 + g * 8 + (lane & 3) * 2;
            float2 v0 = {acc[f][g][0], acc[f][g][1]};
            float2 v1 = {acc[f][g][2], acc[f][g][3]};
            if (EPI == 1) {
                v0.x = siluf(v0.x); v0.y = siluf(v0.y);
                v1.x = siluf(v1.x); v1.y = siluf(v1.y);
            }
            *(float2*)&Cout[row * (long)ldc + col] = v0;
            *(float2*)&Cout[(row + 8) * (long)ldc + col] = v1;
        }
    }
#undef LOADCH
#undef STORECH
}

// ================= scalar FFMA2 sgemm (dt GEMM, K=48) ==========================
template<int EPI>
__global__ void __launch_bounds__(256) sgemm_kernel(
    const float* __restrict__ A, const float* __restrict__ W,
    const float* __restrict__ bias, float* __restrict__ C,
    int K, int lda, int ldw, int ldc)
{
    __shared__ __align__(16) float As[2][8][128];
    __shared__ __align__(16) float Bs[2][8][128];

    const int tid = threadIdx.x;
    const long bm = (long)blockIdx.y * 128;
    const long bn = (long)blockIdx.x * 128;
    const int tx = tid & 15;
    const int ty = tid >> 4;
    const int lr = tid >> 1;
    const int lc = (tid & 1) * 4;

    const float* Ap = A + (bm + lr) * (long)lda + lc;
    const float* Wp = W + (bn + lr) * (long)ldw + lc;

    unsigned long long acc[8][4];
#pragma unroll
    for (int i = 0; i < 8; i++)
#pragma unroll
        for (int j = 0; j < 4; j++) acc[i][j] = 0ULL;

    const int T = K >> 3;
    float4 av = *(const float4*)(Ap);
    float4 wv = *(const float4*)(Wp);
    As[0][lc + 0][lr] = av.x; As[0][lc + 1][lr] = av.y;
    As[0][lc + 2][lr] = av.z; As[0][lc + 3][lr] = av.w;
    Bs[0][lc + 0][lr] = wv.x; Bs[0][lc + 1][lr] = wv.y;
    Bs[0][lc + 2][lr] = wv.z; Bs[0][lc + 3][lr] = wv.w;
    if (T > 1) { av = *(const float4*)(Ap + 8); wv = *(const float4*)(Wp + 8); }
    __syncthreads();

    int p = 0;
    for (int t = 0; t < T; t++) {
        if (t + 1 < T) {
            int q = p ^ 1;
            As[q][lc + 0][lr] = av.x; As[q][lc + 1][lr] = av.y;
            As[q][lc + 2][lr] = av.z; As[q][lc + 3][lr] = av.w;
            Bs[q][lc + 0][lr] = wv.x; Bs[q][lc + 1][lr] = wv.y;
            Bs[q][lc + 2][lr] = wv.z; Bs[q][lc + 3][lr] = wv.w;
        }
        if (t + 2 < T) {
            av = *(const float4*)(Ap + (long)(t + 2) * 8);
            wv = *(const float4*)(Wp + (long)(t + 2) * 8);
        }
#pragma unroll
        for (int k = 0; k < 8; k++) {
            float4 a0 = *(const float4*)&As[p][k][ty * 8];
            float4 a1 = *(const float4*)&As[p][k][ty * 8 + 4];
            ulonglong2 b0 = *(const ulonglong2*)&Bs[p][k][tx * 8];
            ulonglong2 b1 = *(const ulonglong2*)&Bs[p][k][tx * 8 + 4];
            unsigned long long bq[4] = {b0.x, b0.y, b1.x, b1.y};
            float ar[8] = {a0.x, a0.y, a0.z, a0.w, a1.x, a1.y, a1.z, a1.w};
            unsigned long long pa[8];
#pragma unroll
            for (int i = 0; i < 8; i++)
                asm("mov.b64 %0, {%1, %1};" : "=l"(pa[i]) : "f"(ar[i]));
#pragma unroll
            for (int i = 0; i < 8; i++)
#pragma unroll
                for (int j = 0; j < 4; j++)
                    asm("fma.rn.f32x2 %0, %1, %2, %0;"
                        : "+l"(acc[i][j]) : "l"(pa[i]), "l"(bq[j]));
        }
        __syncthreads();
        p ^= 1;
    }

#pragma unroll
    for (int i = 0; i < 8; i++) {
        long m = bm + ty * 8 + i;
#pragma unroll
        for (int j = 0; j < 4; j++) {
            long n = bn + tx * 8 + 2 * j;
            float2 v;
            asm("mov.b64 {%0, %1}, %2;" : "=f"(v.x), "=f"(v.y) : "l"(acc[i][j]));
            if (EPI == 1) { v.x = siluf(v.x); v.y = siluf(v.y); }
            else if (EPI == 2) {
                v.x = softplusf(v.x + bias[n]);
                v.y = softplusf(v.y + bias[n + 1]);
            }
            *(float2*)&C[m * (long)ldc + n] = v;
        }
    }
}

// ---------------- depthwise causal conv (K=4) + SiLU --------------------------
__global__ void conv_kernel(const float* __restrict__ cw, const float* __restrict__ cb)
{
    int idx = blockIdx.x * blockDim.x + threadIdx.x;
    if (idx >= MM * DI) return;
    int d = idx % DI;
    int m = idx / DI;
    int l = m & (LL - 1);
    float acc = cb[d];
#pragma unroll
    for (int k = 0; k < KCONV; k++) {
        int ls = l - (KCONV - 1) + k;
        if (ls >= 0)
            acc = fmaf(g_P[(long)(m - (KCONV - 1) + k) * D2 + d], cw[d * KCONV + k], acc);
    }
    g_HS[idx] = siluf(acc);
}

__global__ void pad_xpw_kernel(const float* __restrict__ xw)
{
    int idx = blockIdx.x * blockDim.x + threadIdx.x;
    if (idx >= 128 * DI) return;
    int n = idx / DI;
    int d = idx % DI;
    g_XPW[idx] = (n < RR + 2 * NSTATE) ? xw[n * DI + d] : 0.f;
}

// ---------------- reduce split-K partials into SSMP ----------------------------
__global__ void spxsum_kernel()
{
    int idx = blockIdx.x * blockDim.x + threadIdx.x;
    if (idx >= MM * 128) return;
    float s = 0.f;
#pragma unroll
    for (int j = 0; j < NSPLIT; j++) s += g_SPX[(size_t)j * MM * 128 + idx];
    g_SSMP[idx] = s;
}

__global__ void scan_kernel(const float* __restrict__ A_log)
{
    int t = blockIdx.x * blockDim.x + threadIdx.x;
    int gid = t >> 4;
    int n = t & 15;
    if (gid >= BB * DI) return;
    int b = gid / DI;
    int d = gid - b * DI;

    float An = -__expf(A_log[d * NSTATE + n]);
    float s = 0.f;
    const float* dtp = g_DT + (long)b * LL * DI + d;
    const float* hsp = g_HS + (long)b * LL * DI + d;
    const float* sp  = g_SSMP + (long)b * LL * 128;
    float* yp = g_YS + (long)b * LL * DI + d;

    for (int l = 0; l < LL; l++) {
        float dtv = dtp[(long)l * DI];
        float hv  = hsp[(long)l * DI];
        float bv  = sp[l * 128 + RR + n];
        float cv  = sp[l * 128 + RR + NSTATE + n];
        s = fmaf(__expf(dtv * An), s, dtv * bv * hv);
        float p = s * cv;
        p += __shfl_xor_sync(0xffffffffu, p, 8);
        p += __shfl_xor_sync(0xffffffffu, p, 4);
        p += __shfl_xor_sync(0xffffffffu, p, 2);
        p += __shfl_xor_sync(0xffffffffu, p, 1);
        if (n == 0) yp[(long)l * DI] = p;
    }
}

__global__ void combine_kernel(const float* __restrict__ Dv)
{
    int idx = blockIdx.x * blockDim.x + threadIdx.x;
    if (idx >= MM * DI) return;
    int d = idx % DI;
    int m = idx / DI;
    float g = g_P[(long)m * D2 + DI + d];
    g_Y[idx] = (g_YS[idx] + g_HS[idx] * Dv[d]) * siluf(g);
}

// ---------------- launch ------------------------------------------------------
extern "C" void kernel_launch(void* const* d_in, const int* in_sizes, int n_in,
                              void* d_out, int out_size)
{
    const float* x    = (const float*)d_in[0];
    const float* iuw  = (const float*)d_in[1];
    const float* idw  = (const float*)d_in[2];
    const float* cw   = (const float*)d_in[3];
    const float* cb   = (const float*)d_in[4];
    const float* xpw  = (const float*)d_in[5];
    const float* dtw  = (const float*)d_in[6];
    const float* dtb  = (const float*)d_in[7];
    const float* alog = (const float*)d_in[8];
    const float* Dv   = (const float*)d_in[9];
    const float* ouw  = (const float*)d_in[10];
    const float* odw  = (const float*)d_in[11];
    float* out = (float*)d_out;

    float *T1, *P, *HS, *XPW, *SPX, *SSMP, *DT, *YS, *Y, *T4;
    cudaGetSymbolAddress((void**)&T1,   g_T1);
    cudaGetSymbolAddress((void**)&P,    g_P);
    cudaGetSymbolAddress((void**)&HS,   g_HS);
    cudaGetSymbolAddress((void**)&XPW,  g_XPW);
    cudaGetSymbolAddress((void**)&SPX,  g_SPX);
    cudaGetSymbolAddress((void**)&SSMP, g_SSMP);
    cudaGetSymbolAddress((void**)&DT,   g_DT);
    cudaGetSymbolAddress((void**)&YS,   g_YS);
    cudaGetSymbolAddress((void**)&Y,    g_Y);
    cudaGetSymbolAddress((void**)&T4,   g_T4);

    cudaFuncSetAttribute(hgemm_kernel<0>, cudaFuncAttributeMaxDynamicSharedMemorySize, HSMEM);
    cudaFuncSetAttribute(hgemm_kernel<1>, cudaFuncAttributeMaxDynamicSharedMemorySize, HSMEM);

    // 1) T1 = silu(x @ in_up_w^T)              [2048,12288] K=768
    hgemm_kernel<1><<<dim3(D1/128, MM/128, 1), 256, HSMEM>>>(x, iuw, T1, HH, HH, D1, HH, 0);
    // 2) P = T1 @ in_down_w^T                  [2048,3072] K=12288
    hgemm_kernel<0><<<dim3(D2/128, MM/128, 1), 256, HSMEM>>>(T1, idw, P, D1, D1, D2, D1, 0);
    // 3) HS = silu(causal depthwise conv + b)
    conv_kernel<<<(MM*DI + 255)/256, 256>>>(cw, cb);
    // 4) pad x_proj_w to 128 rows
    pad_xpw_kernel<<<(128*DI + 255)/256, 256>>>(xpw);
    // 5) SSMP = HS @ XPW^T  (split-K x8 for parallelism, then reduce)
    hgemm_kernel<0><<<dim3(1, MM/128, NSPLIT), 256, HSMEM>>>(HS, XPW, SPX, DI, DI, 128,
                                                             DI/NSPLIT, (long)MM*128);
    spxsum_kernel<<<(MM*128 + 255)/256, 256>>>();
    // 6) DT = softplus(SSMP[:, :48] @ dt_w^T + dt_b)
    sgemm_kernel<2><<<dim3(DI/128, MM/128), 256>>>(SSMP, dtw, dtb, DT, RR, 128, RR, DI);
    // 7) selective scan -> YS
    scan_kernel<<<(BB*DI*16 + 255)/256, 256>>>(alog);
    // 8) Y = (YS + HS*D) * silu(gate)
    combine_kernel<<<(MM*DI + 255)/256, 256>>>(Dv);
    // 9) T4 = silu(Y @ out_up_w^T)             [2048,6144] K=1536
    hgemm_kernel<1><<<dim3(D3/128, MM/128, 1), 256, HSMEM>>>(Y, ouw, T4, DI, DI, D3, DI, 0);
    // 10) out = T4 @ out_down_w^T              [2048,768] K=6144
    hgemm_kernel<0><<<dim3(HH/128, MM/128, 1), 256, HSMEM>>>(T4, odw, out, D3, D3, HH, D3, 0);
}